// round 7
// baseline (speedup 1.0000x reference)
#include <cuda_runtime.h>
#include <cuda_fp16.h>
#include <cstdint>

// ---------------------------------------------------------------------------
// ExtractNet (MMoE/PLE): 12 expert MLPs (256->64->64->64) + per-task softmax
// gates. fp16 mma.sync.m16n8k16, fp32 accum.
// 128 rows/CTA, 8 warps = 4mw x 2nw, warp tile m32n32, 1 CTA/SM.
// X A-fragments half-cached in registers; pair-scoped named barriers.
// ---------------------------------------------------------------------------

#define NE 12

// Packed weights: u32 = half2 in exact B-fragment order
__device__ unsigned g_W1p[NE * 8192];   // per expert: 16ks x 8nt x 64
__device__ unsigned g_W2p[NE * 2048];   // 4ks x 8nt x 64
__device__ unsigned g_W3p[NE * 2048];
__device__ unsigned g_Wgp[2048];        // gates: 16ks x 2slot x 64
__device__ float g_b1[NE * 64];
__device__ float g_b2[NE * 64];
__device__ float g_b3[NE * 64];
__device__ float g_bg[16];

__device__ __forceinline__ unsigned packh2(float a, float b) {
    __half2 h = __floats2half2_rn(a, b);
    return *reinterpret_cast<unsigned*>(&h);
}

__device__ __forceinline__ uint32_t smem_to_u32(const void* p) {
    uint32_t a;
    asm("{ .reg .u64 t; cvta.to.shared.u64 t, %1; cvt.u32.u64 %0, t; }"
        : "=r"(a) : "l"(p));
    return a;
}

// m16n8k16 fp16 mma, fp32 accum.  lane = gy*4+gx
__device__ __forceinline__ void mma16(float c[4], unsigned a0, unsigned a1,
                                      unsigned a2, unsigned a3,
                                      unsigned b0, unsigned b1) {
    asm volatile(
        "mma.sync.aligned.m16n8k16.row.col.f32.f16.f16.f32 "
        "{%0,%1,%2,%3}, {%4,%5,%6,%7}, {%8,%9}, {%0,%1,%2,%3};\n"
        : "+f"(c[0]), "+f"(c[1]), "+f"(c[2]), "+f"(c[3])
        : "r"(a0), "r"(a1), "r"(a2), "r"(a3), "r"(b0), "r"(b1));
}

__device__ __forceinline__ void cp16(uint32_t dst, const void* src) {
    asm volatile("cp.async.cg.shared.global [%0], [%1], 16;" :: "r"(dst), "l"(src));
}
#define CP_COMMIT() asm volatile("cp.async.commit_group;" ::: "memory")
#define CP_WAIT0()  asm volatile("cp.async.wait_group 0;" ::: "memory")
#define PAIR_BAR(id) asm volatile("bar.sync %0, 64;" :: "r"(id) : "memory")

// ------------------------- weight packing kernels --------------------------
// Dest u32 index within expert: (ks*8 + nt)*64 + lane*2 + j
// value = half2( W[k0][n], W[k0+1][n] ), k0 = ks*16 + j*8 + 2gx, n = nt*8 + gy

__global__ void pack_w1(const float* __restrict__ wt, const float* __restrict__ ws) {
    int idx = blockIdx.x * blockDim.x + threadIdx.x;
    if (idx >= NE * 8192) return;
    int e = idx >> 13, p = idx & 8191;
    int ks = p >> 9, rem = p & 511, nt = rem >> 6, q = rem & 63;
    int lane = q >> 1, j = q & 1;
    int gy = lane >> 2, gx = lane & 3;
    int k0 = ks * 16 + j * 8 + 2 * gx, n = nt * 8 + gy;
    const float* src = (e < 8) ? wt + e * 16384 : ws + (e - 8) * 16384;
    g_W1p[idx] = packh2(src[k0 * 64 + n], src[(k0 + 1) * 64 + n]);
}

__global__ void pack_w23(const float* __restrict__ wt, const float* __restrict__ ws,
                         int which) {
    int idx = blockIdx.x * blockDim.x + threadIdx.x;
    if (idx >= NE * 2048) return;
    int e = idx >> 11, p = idx & 2047;
    int ks = p >> 9, rem = p & 511, nt = rem >> 6, q = rem & 63;
    int lane = q >> 1, j = q & 1;
    int gy = lane >> 2, gx = lane & 3;
    int k0 = ks * 16 + j * 8 + 2 * gx, n = nt * 8 + gy;
    const float* src = (e < 8) ? wt + e * 4096 : ws + (e - 8) * 4096;
    unsigned v = packh2(src[k0 * 64 + n], src[(k0 + 1) * 64 + n]);
    if (which) g_W3p[idx] = v; else g_W2p[idx] = v;
}

__global__ void pack_wg(const float* __restrict__ wg) {
    int idx = blockIdx.x * blockDim.x + threadIdx.x;
    if (idx >= 2048) return;
    int ks = idx >> 7, rem = idx & 127, t = rem >> 6, q = rem & 63;
    int lane = q >> 1, j = q & 1;
    int gy = lane >> 2, gx = lane & 3;
    int k0 = ks * 16 + j * 8 + 2 * gx;
    g_Wgp[idx] = packh2(wg[t * 2048 + k0 * 8 + gy], wg[t * 2048 + (k0 + 1) * 8 + gy]);
}

__global__ void pack_bias(const float* bt1, const float* bs1,
                          const float* bt2, const float* bs2,
                          const float* bt3, const float* bs3, const float* bg) {
    int i = blockIdx.x * blockDim.x + threadIdx.x;
    if (i < 768) g_b1[i] = (i < 512) ? bt1[i] : bs1[i - 512];
    else if (i < 1536) { int j = i - 768;  g_b2[j] = (j < 512) ? bt2[j] : bs2[j - 512]; }
    else if (i < 2304) { int j = i - 1536; g_b3[j] = (j < 512) ? bt3[j] : bs3[j - 512]; }
    else if (i < 2320) g_bg[i - 2304] = bg[i - 2304];
}

// ------------------------------ main kernel --------------------------------
// smem u32 offsets
#define U_XP 0        // 16384: X packed A-frags (16ks x 8mt x 128), lane-rotated
#define U_W1 16384    // 2 x 8192 double-buffered
#define U_W2 32768    // 2 x 2048
#define U_W3 36864    // 2 x 2048
#define U_HA 40960    // 4 mw x 1024  (8 blks x 128)
#define U_HB 45056    // 4 mw x 1024  (Wg staged in first 2048 during gate phase)
#define U_GT 49152    // 2176 floats (gate probs, 128 rows x stride 17)
#define U_B  51328    // biases: b1 768, b2 768, b3 768, bg 16 = 2320 floats
#define U_TOT 53648   // 214,592 B -> 1 CTA/SM

__global__ __launch_bounds__(256, 1)
void moe_main(const float* __restrict__ X, float* __restrict__ out) {
    extern __shared__ unsigned sm[];
    const int tid = threadIdx.x, wid = tid >> 5, lane = tid & 31;
    const int gy = lane >> 2, gx = lane & 3;
    const int mw = wid >> 1, nw = wid & 1;
    const size_t rowbase = (size_t)blockIdx.x * 128;

    unsigned* Xp  = sm + U_XP;
    unsigned* hA  = sm + U_HA + mw * 1024;   // this pair's region
    unsigned* hB  = sm + U_HB + mw * 1024;
    float* gts  = reinterpret_cast<float*>(sm + U_GT);
    float* bias = reinterpret_cast<float*>(sm + U_B);
    const uint32_t sb = smem_to_u32(sm);

    // ---- initial prefetch: Wg -> U_HB, expert0 weights -> buf0 ----
    {
        const uint4* sg = reinterpret_cast<const uint4*>(g_Wgp);
#pragma unroll
        for (int i = 0; i < 2; ++i)
            cp16(sb + (U_HB << 2) + (tid + i * 256) * 16, sg + tid + i * 256);
        const uint4* s1 = reinterpret_cast<const uint4*>(g_W1p);
#pragma unroll
        for (int i = 0; i < 8; ++i)
            cp16(sb + (U_W1 << 2) + (tid + i * 256) * 16, s1 + tid + i * 256);
        const uint4* s2 = reinterpret_cast<const uint4*>(g_W2p);
#pragma unroll
        for (int i = 0; i < 2; ++i)
            cp16(sb + (U_W2 << 2) + (tid + i * 256) * 16, s2 + tid + i * 256);
        const uint4* s3 = reinterpret_cast<const uint4*>(g_W3p);
#pragma unroll
        for (int i = 0; i < 2; ++i)
            cp16(sb + (U_W3 << 2) + (tid + i * 256) * 16, s3 + tid + i * 256);
        CP_COMMIT();
    }

    // ---- stage biases ----
    for (int i = tid; i < 768; i += 256) {
        bias[i]        = g_b1[i];
        bias[768 + i]  = g_b2[i];
        bias[1536 + i] = g_b3[i];
    }
    if (tid < 16) bias[2304 + tid] = g_bg[tid];

    // ---- stage X: gmem (coalesced float4) -> packed fp16 A-frags ----
    {
        const float4* xg = reinterpret_cast<const float4*>(X + rowbase * 256);
#pragma unroll
        for (int it = 0; it < 32; ++it) {
            int g = tid + it * 256;              // float4 id, row-major (128x64)
            float4 v = xg[g];
            int r = g >> 6, c4 = g & 63;
            int ks = c4 >> 2, kk = (c4 & 3) * 4;
            int mt = r >> 4, rl = r & 15;
            int jr = (rl >= 8) ? 1 : 0, gyy = rl & 7;
            int gxp = (kk & 7) >> 1;
            int j0 = jr + ((kk & 8) ? 2 : 0);
            int blk = ks * 8 + mt;
            int fl0 = gyy * 4 + gxp;
            Xp[blk * 128 + (((fl0     + blk * 4) & 31) << 2) + j0] = packh2(v.x, v.y);
            Xp[blk * 128 + (((fl0 + 1 + blk * 4) & 31) << 2) + j0] = packh2(v.z, v.w);
        }
    }
    CP_WAIT0();
    __syncthreads();

    // ---- cache X A-frags for ks 0..7 in registers (warp tile m32: 2 mtiles) ----
    uint4 XA[8][2];
#pragma unroll
    for (int ks = 0; ks < 8; ++ks)
#pragma unroll
        for (int mtl = 0; mtl < 2; ++mtl) {
            int blk = ks * 8 + mw * 2 + mtl;
            XA[ks][mtl] = *reinterpret_cast<const uint4*>(
                Xp + blk * 128 + (((lane + blk * 4) & 31) << 2));
        }

    // ---- gate logits: warp w -> rows w*16..w*16+15, all 16 cols ----
    {
        const unsigned* Wg = sm + U_HB;
        float c[2][4] = {};
#pragma unroll
        for (int ks = 0; ks < 16; ++ks) {
            int blk = ks * 8 + wid;
            uint4 A = *reinterpret_cast<const uint4*>(
                Xp + blk * 128 + (((lane + blk * 4) & 31) << 2));
#pragma unroll
            for (int s = 0; s < 2; ++s) {
                uint2 B = *reinterpret_cast<const uint2*>(Wg + (ks * 2 + s) * 64 + lane * 2);
                mma16(c[s], A.x, A.y, A.z, A.w, B.x, B.y);
            }
        }
        int r0 = wid * 16 + gy;
#pragma unroll
        for (int s = 0; s < 2; ++s) {
            int col = s * 8 + 2 * gx;
            gts[r0 * 17 + col]           = c[s][0] + bias[2304 + col];
            gts[r0 * 17 + col + 1]       = c[s][1] + bias[2304 + col + 1];
            gts[(r0 + 8) * 17 + col]     = c[s][2] + bias[2304 + col];
            gts[(r0 + 8) * 17 + col + 1] = c[s][3] + bias[2304 + col + 1];
        }
    }
    __syncthreads();

    // ---- softmax per (row, task): 256 threads, one each ----
    {
        int r = tid >> 1, t = tid & 1;
        float* p = gts + r * 17 + t * 8;
        float m = p[0];
#pragma unroll
        for (int i = 1; i < 8; ++i) m = fmaxf(m, p[i]);
        float e8[8]; float s = 0.f;
#pragma unroll
        for (int i = 0; i < 8; ++i) { e8[i] = __expf(p[i] - m); s += e8[i]; }
        float inv = 1.f / s;
#pragma unroll
        for (int i = 0; i < 8; ++i) p[i] = e8[i] * inv;
    }
    __syncthreads();   // gts visible; Wg reads done before hB overwritten

    float acc0[2][16], acc1[2][16];
#pragma unroll
    for (int m2 = 0; m2 < 2; ++m2)
#pragma unroll
        for (int i = 0; i < 16; ++i) { acc0[m2][i] = 0.f; acc1[m2][i] = 0.f; }

    const int barid = 1 + mw;

    // ---- expert loop ----
    for (int e = 0; e < NE; ++e) {
        if (e) { CP_WAIT0(); __syncthreads(); }
        const int buf = e & 1;
        const unsigned* W1s = sm + U_W1 + buf * 8192;
        const unsigned* W2s = sm + U_W2 + buf * 2048;
        const unsigned* W3s = sm + U_W3 + buf * 2048;

        if (e + 1 < NE) {   // prefetch next expert into other buffer
            int nb = buf ^ 1;
            const uint4* s1 = reinterpret_cast<const uint4*>(g_W1p) + (e + 1) * 2048;
            uint32_t d1 = sb + ((U_W1 + nb * 8192) << 2);
#pragma unroll
            for (int i = 0; i < 8; ++i)
                cp16(d1 + (tid + i * 256) * 16, s1 + tid + i * 256);
            const uint4* s2 = reinterpret_cast<const uint4*>(g_W2p) + (e + 1) * 512;
            uint32_t d2 = sb + ((U_W2 + nb * 2048) << 2);
#pragma unroll
            for (int i = 0; i < 2; ++i)
                cp16(d2 + (tid + i * 256) * 16, s2 + tid + i * 256);
            const uint4* s3 = reinterpret_cast<const uint4*>(g_W3p) + (e + 1) * 512;
            uint32_t d3 = sb + ((U_W3 + nb * 2048) << 2);
#pragma unroll
            for (int i = 0; i < 2; ++i)
                cp16(d3 + (tid + i * 256) * 16, s3 + tid + i * 256);
            CP_COMMIT();
        }

        // ---- L1: [128,256] x W1^T, warp m32n32, 16 ksteps ----
        float c1[2][4][4] = {};
#pragma unroll
        for (int ks = 0; ks < 16; ++ks) {
            uint2 B[4];
#pragma unroll
            for (int nt = 0; nt < 4; ++nt)
                B[nt] = *reinterpret_cast<const uint2*>(
                    W1s + (ks * 8 + nw * 4 + nt) * 64 + lane * 2);
            uint4 A0, A1;
            if (ks < 8) { A0 = XA[ks][0]; A1 = XA[ks][1]; }
            else {
                int b0 = ks * 8 + mw * 2, b1 = b0 + 1;
                A0 = *reinterpret_cast<const uint4*>(
                    Xp + b0 * 128 + (((lane + b0 * 4) & 31) << 2));
                A1 = *reinterpret_cast<const uint4*>(
                    Xp + b1 * 128 + (((lane + b1 * 4) & 31) << 2));
            }
#pragma unroll
            for (int nt = 0; nt < 4; ++nt) {
                mma16(c1[0][nt], A0.x, A0.y, A0.z, A0.w, B[nt].x, B[nt].y);
                mma16(c1[1][nt], A1.x, A1.y, A1.z, A1.w, B[nt].x, B[nt].y);
            }
        }
        // epilogue 1: bias+relu -> hA (packed A-frag layout)
        {
            const float* b = bias + e * 64;
#pragma unroll
            for (int mtl = 0; mtl < 2; ++mtl)
#pragma unroll
                for (int nt = 0; nt < 4; ++nt) {
                    int col = nw * 32 + nt * 8 + 2 * gx;
                    float b0 = b[col], b1v = b[col + 1];
                    unsigned lo = packh2(fmaxf(c1[mtl][nt][0] + b0, 0.f),
                                         fmaxf(c1[mtl][nt][1] + b1v, 0.f));
                    unsigned hi = packh2(fmaxf(c1[mtl][nt][2] + b0, 0.f),
                                         fmaxf(c1[mtl][nt][3] + b1v, 0.f));
                    int ks2 = (nw * 4 + nt) >> 1, jb = (nt & 1) * 2;
                    *reinterpret_cast<uint2*>(hA + (ks2 * 2 + mtl) * 128 + lane * 4 + jb) =
                        make_uint2(lo, hi);
                }
        }
        PAIR_BAR(barid);

        // ---- L2: K=64, 4 ksteps ----
        float c2[2][4][4] = {};
#pragma unroll
        for (int ks = 0; ks < 4; ++ks) {
            uint2 B[4];
#pragma unroll
            for (int nt = 0; nt < 4; ++nt)
                B[nt] = *reinterpret_cast<const uint2*>(
                    W2s + (ks * 8 + nw * 4 + nt) * 64 + lane * 2);
            uint4 A0 = *reinterpret_cast<const uint4*>(hA + (ks * 2 + 0) * 128 + lane * 4);
            uint4 A1 = *reinterpret_cast<const uint4*>(hA + (ks * 2 + 1) * 128 + lane * 4);
#pragma unroll
            for (int nt = 0; nt < 4; ++nt) {
                mma16(c2[0][nt], A0.x, A0.y, A0.z, A0.w, B[nt].x, B[nt].y);
                mma16(c2[1][nt], A1.x, A1.y, A1.z, A1.w, B[nt].x, B[nt].y);
            }
        }
        {
            const float* b = bias + 768 + e * 64;
#pragma unroll
            for (int mtl = 0; mtl < 2; ++mtl)
#pragma unroll
                for (int nt = 0; nt < 4; ++nt) {
                    int col = nw * 32 + nt * 8 + 2 * gx;
                    float b0 = b[col], b1v = b[col + 1];
                    unsigned lo = packh2(fmaxf(c2[mtl][nt][0] + b0, 0.f),
                                         fmaxf(c2[mtl][nt][1] + b1v, 0.f));
                    unsigned hi = packh2(fmaxf(c2[mtl][nt][2] + b0, 0.f),
                                         fmaxf(c2[mtl][nt][3] + b1v, 0.f));
                    int ks2 = (nw * 4 + nt) >> 1, jb = (nt & 1) * 2;
                    *reinterpret_cast<uint2*>(hB + (ks2 * 2 + mtl) * 128 + lane * 4 + jb) =
                        make_uint2(lo, hi);
                }
        }
        PAIR_BAR(barid);

        // ---- L3 ----
        float c3[2][4][4] = {};
#pragma unroll
        for (int ks = 0; ks < 4; ++ks) {
            uint2 B[4];
#pragma unroll
            for (int nt = 0; nt < 4; ++nt)
                B[nt] = *reinterpret_cast<const uint2*>(
                    W3s + (ks * 8 + nw * 4 + nt) * 64 + lane * 2);
            uint4 A0 = *reinterpret_cast<const uint4*>(hB + (ks * 2 + 0) * 128 + lane * 4);
            uint4 A1 = *reinterpret_cast<const uint4*>(hB + (ks * 2 + 1) * 128 + lane * 4);
#pragma unroll
            for (int nt = 0; nt < 4; ++nt) {
                mma16(c3[0][nt], A0.x, A0.y, A0.z, A0.w, B[nt].x, B[nt].y);
                mma16(c3[1][nt], A1.x, A1.y, A1.z, A1.w, B[nt].x, B[nt].y);
            }
        }
        // epilogue 3: bias + gated accumulate
        {
            const float* b = bias + 1536 + e * 64;
#pragma unroll
            for (int mtl = 0; mtl < 2; ++mtl) {
                int r0 = mw * 32 + mtl * 16 + gy;
                if (e < 8) {
                    int t = e >> 2, gi = e & 3;
                    float g0 = gts[r0 * 17 + t * 8 + gi];
                    float g1 = gts[(r0 + 8) * 17 + t * 8 + gi];
                    float (*ac)[16] = (e < 4) ? acc0 : acc1;
#pragma unroll
                    for (int nt = 0; nt < 4; ++nt) {
                        int col = nw * 32 + nt * 8 + 2 * gx;
                        float b0 = b[col], b1v = b[col + 1];
                        ac[mtl][nt * 4 + 0] += g0 * (c3[mtl][nt][0] + b0);
                        ac[mtl][nt * 4 + 1] += g0 * (c3[mtl][nt][1] + b1v);
                        ac[mtl][nt * 4 + 2] += g1 * (c3[mtl][nt][2] + b0);
                        ac[mtl][nt * 4 + 3] += g1 * (c3[mtl][nt][3] + b1v);
                    }
                } else {
                    float ga0 = gts[r0 * 17 + (e - 4)];
                    float ga1 = gts[(r0 + 8) * 17 + (e - 4)];
                    float gb0 = gts[r0 * 17 + (e + 4)];
                    float gb1 = gts[(r0 + 8) * 17 + (e + 4)];
#pragma unroll
                    for (int nt = 0; nt < 4; ++nt) {
                        int col = nw * 32 + nt * 8 + 2 * gx;
                        float b0 = b[col], b1v = b[col + 1];
                        float v0 = c3[mtl][nt][0] + b0, v1 = c3[mtl][nt][1] + b1v;
                        float v2 = c3[mtl][nt][2] + b0, v3 = c3[mtl][nt][3] + b1v;
                        acc0[mtl][nt * 4 + 0] += ga0 * v0; acc1[mtl][nt * 4 + 0] += gb0 * v0;
                        acc0[mtl][nt * 4 + 1] += ga0 * v1; acc1[mtl][nt * 4 + 1] += gb0 * v1;
                        acc0[mtl][nt * 4 + 2] += ga1 * v2; acc1[mtl][nt * 4 + 2] += gb1 * v2;
                        acc0[mtl][nt * 4 + 3] += ga1 * v3; acc1[mtl][nt * 4 + 3] += gb1 * v3;
                    }
                }
            }
        }
    }

    __syncthreads();
    // ---- output: stage fp32 (stride 136), then coalesced float4 ----
    {
        float* ost = reinterpret_cast<float*>(sm);   // reuses Xp+W1 region
#pragma unroll
        for (int mtl = 0; mtl < 2; ++mtl) {
            int r0 = mw * 32 + mtl * 16 + gy;
#pragma unroll
            for (int nt = 0; nt < 4; ++nt) {
                int col0 = nw * 32 + nt * 8 + 2 * gx;
                *reinterpret_cast<float2*>(ost + r0 * 136 + col0) =
                    make_float2(acc0[mtl][nt * 4 + 0], acc0[mtl][nt * 4 + 1]);
                *reinterpret_cast<float2*>(ost + (r0 + 8) * 136 + col0) =
                    make_float2(acc0[mtl][nt * 4 + 2], acc0[mtl][nt * 4 + 3]);
                int col1 = 64 + col0;
                *reinterpret_cast<float2*>(ost + r0 * 136 + col1) =
                    make_float2(acc1[mtl][nt * 4 + 0], acc1[mtl][nt * 4 + 1]);
                *reinterpret_cast<float2*>(ost + (r0 + 8) * 136 + col1) =
                    make_float2(acc1[mtl][nt * 4 + 2], acc1[mtl][nt * 4 + 3]);
            }
        }
    }
    __syncthreads();
    {
        float4* og = reinterpret_cast<float4*>(out + rowbase * 128);
        const float* ost = reinterpret_cast<const float*>(sm);
#pragma unroll
        for (int it = 0; it < 16; ++it) {
            int g = tid + it * 256;
            int rr = g >> 5, q = g & 31;
            og[g] = *reinterpret_cast<const float4*>(ost + rr * 136 + q * 4);
        }
    }
}

// ------------------------------- launcher ----------------------------------
extern "C" void kernel_launch(void* const* d_in, const int* in_sizes, int n_in,
                              void* d_out, int out_size) {
    const float* X   = (const float*)d_in[0];
    const float* Wt1 = (const float*)d_in[1];
    const float* bt1 = (const float*)d_in[2];
    const float* Wt2 = (const float*)d_in[3];
    const float* bt2 = (const float*)d_in[4];
    const float* Wt3 = (const float*)d_in[5];
    const float* bt3 = (const float*)d_in[6];
    const float* Ws1 = (const float*)d_in[7];
    const float* bs1 = (const float*)d_in[8];
    const float* Ws2 = (const float*)d_in[9];
    const float* bs2 = (const float*)d_in[10];
    const float* Ws3 = (const float*)d_in[11];
    const float* bs3 = (const float*)d_in[12];
    const float* Wg  = (const float*)d_in[13];
    const float* bg  = (const float*)d_in[14];
    float* out = (float*)d_out;

    pack_w1<<<(NE * 8192 + 255) / 256, 256>>>(Wt1, Ws1);
    pack_w23<<<(NE * 2048 + 255) / 256, 256>>>(Wt2, Ws2, 0);
    pack_w23<<<(NE * 2048 + 255) / 256, 256>>>(Wt3, Ws3, 1);
    pack_wg<<<8, 256>>>(Wg);
    pack_bias<<<10, 256>>>(bt1, bs1, bt2, bs2, bt3, bs3, bg);

    cudaFuncSetAttribute(moe_main, cudaFuncAttributeMaxDynamicSharedMemorySize,
                         U_TOT * (int)sizeof(unsigned));
    moe_main<<<65536 / 128, 256, U_TOT * sizeof(unsigned)>>>(X, out);
}

// round 8
// speedup vs baseline: 1.5085x; 1.5085x over previous
#include <cuda_runtime.h>
#include <cuda_fp16.h>
#include <cstdint>

// ---------------------------------------------------------------------------
// ExtractNet (MMoE/PLE): 12 expert MLPs (256->64->64->64) + per-task softmax
// gates. fp16 mma.sync.m16n8k16, fp32 accum. 64 rows/CTA, 8 warps, 2 CTA/SM.
// R5 structure + single fused pack kernel + split prologue commit groups.
// ---------------------------------------------------------------------------

#define NE 12

// Packed weights: u32 = half2 in exact B-fragment order
__device__ unsigned g_W1p[NE * 8192];   // per expert: 16ks x 8nt x 64
__device__ unsigned g_W2p[NE * 2048];   // 4ks x 8nt x 64
__device__ unsigned g_W3p[NE * 2048];
__device__ unsigned g_Wgp[2048];        // gates: 16ks x 2slot x 64
__device__ float g_b1[NE * 64];
__device__ float g_b2[NE * 64];
__device__ float g_b3[NE * 64];
__device__ float g_bg[16];

__device__ __forceinline__ unsigned packh2(float a, float b) {
    __half2 h = __floats2half2_rn(a, b);
    return *reinterpret_cast<unsigned*>(&h);
}

__device__ __forceinline__ uint32_t smem_to_u32(const void* p) {
    uint32_t a;
    asm("{ .reg .u64 t; cvta.to.shared.u64 t, %1; cvt.u32.u64 %0, t; }"
        : "=r"(a) : "l"(p));
    return a;
}

// m16n8k16 fp16 mma, fp32 accum.  lane = gy*4+gx
__device__ __forceinline__ void mma16(float c[4], unsigned a0, unsigned a1,
                                      unsigned a2, unsigned a3,
                                      unsigned b0, unsigned b1) {
    asm volatile(
        "mma.sync.aligned.m16n8k16.row.col.f32.f16.f16.f32 "
        "{%0,%1,%2,%3}, {%4,%5,%6,%7}, {%8,%9}, {%0,%1,%2,%3};\n"
        : "+f"(c[0]), "+f"(c[1]), "+f"(c[2]), "+f"(c[3])
        : "r"(a0), "r"(a1), "r"(a2), "r"(a3), "r"(b0), "r"(b1));
}

__device__ __forceinline__ void cp16(uint32_t dst, const void* src) {
    asm volatile("cp.async.cg.shared.global [%0], [%1], 16;" :: "r"(dst), "l"(src));
}
#define CP_COMMIT() asm volatile("cp.async.commit_group;" ::: "memory")
#define CP_WAIT0()  asm volatile("cp.async.wait_group 0;" ::: "memory")
#define CP_WAIT1()  asm volatile("cp.async.wait_group 1;" ::: "memory")

// ------------------------- fused weight packing ----------------------------
// One kernel for all weight/bias repacking (replaces 5 launches).
// B-frag dest u32 index within expert: (ks*8 + nt)*64 + lane*2 + j
// value = half2( W[k0][n], W[k0+1][n] ), k0 = ks*16 + j*8 + 2gx, n = nt*8 + gy

#define PK_W1 (NE * 8192)
#define PK_W2 (PK_W1 + NE * 2048)
#define PK_W3 (PK_W2 + NE * 2048)
#define PK_WG (PK_W3 + 2048)
#define PK_END (PK_WG + 2320)

__global__ void pack_all(const float* __restrict__ Wt1, const float* __restrict__ Wt2,
                         const float* __restrict__ Wt3, const float* __restrict__ Ws1,
                         const float* __restrict__ Ws2, const float* __restrict__ Ws3,
                         const float* __restrict__ Wg,
                         const float* __restrict__ bt1, const float* __restrict__ bt2,
                         const float* __restrict__ bt3, const float* __restrict__ bs1,
                         const float* __restrict__ bs2, const float* __restrict__ bs3,
                         const float* __restrict__ bg) {
    int idx = blockIdx.x * blockDim.x + threadIdx.x;
    if (idx < PK_W1) {
        int e = idx >> 13, p = idx & 8191;
        int ks = p >> 9, rem = p & 511, nt = rem >> 6, q = rem & 63;
        int lane = q >> 1, j = q & 1;
        int gy = lane >> 2, gx = lane & 3;
        int k0 = ks * 16 + j * 8 + 2 * gx, n = nt * 8 + gy;
        const float* src = (e < 8) ? Wt1 + e * 16384 : Ws1 + (e - 8) * 16384;
        g_W1p[idx] = packh2(src[k0 * 64 + n], src[(k0 + 1) * 64 + n]);
    } else if (idx < PK_W3) {
        int which = (idx >= PK_W2);
        int i2 = idx - (which ? PK_W2 : PK_W1);
        int e = i2 >> 11, p = i2 & 2047;
        int ks = p >> 9, rem = p & 511, nt = rem >> 6, q = rem & 63;
        int lane = q >> 1, j = q & 1;
        int gy = lane >> 2, gx = lane & 3;
        int k0 = ks * 16 + j * 8 + 2 * gx, n = nt * 8 + gy;
        const float* wt = which ? Wt3 : Wt2;
        const float* ws = which ? Ws3 : Ws2;
        const float* src = (e < 8) ? wt + e * 4096 : ws + (e - 8) * 4096;
        unsigned v = packh2(src[k0 * 64 + n], src[(k0 + 1) * 64 + n]);
        if (which) g_W3p[i2] = v; else g_W2p[i2] = v;
    } else if (idx < PK_WG) {
        int i2 = idx - PK_W3;
        int ks = i2 >> 7, rem = i2 & 127, t = rem >> 6, q = rem & 63;
        int lane = q >> 1, j = q & 1;
        int gy = lane >> 2, gx = lane & 3;
        int k0 = ks * 16 + j * 8 + 2 * gx;
        g_Wgp[i2] = packh2(Wg[t * 2048 + k0 * 8 + gy], Wg[t * 2048 + (k0 + 1) * 8 + gy]);
    } else if (idx < PK_END) {
        int i = idx - PK_WG;
        if (i < 768) g_b1[i] = (i < 512) ? bt1[i] : bs1[i - 512];
        else if (i < 1536) { int j = i - 768;  g_b2[j] = (j < 512) ? bt2[j] : bs2[j - 512]; }
        else if (i < 2304) { int j = i - 1536; g_b3[j] = (j < 512) ? bt3[j] : bs3[j - 512]; }
        else g_bg[i - 2304] = bg[i - 2304];
    }
}

// ------------------------------ main kernel --------------------------------
// smem u32 offsets
#define U_XP 0        // 8192: X packed A-frags (16ks x 4mt x 128), lane-rotated
#define U_W1 8192     // 8192 (single buffer; out-staging after loop)
#define U_W2 16384    // 2048 (single)
#define U_W3 18432    // 2 x 2048 (double)
#define U_HA 22528    // 2048 (aliases Wg during gate phase)
#define U_HB 24576    // 2048
#define U_GT 26624    // 1088 floats (gate probs, stride 17)
#define U_TOT 27712   // 110,848 B -> 2 CTAs/SM

__device__ __forceinline__ unsigned xp_idx4(int blk, int lane) {
    return blk * 128 + (((lane + blk * 4) & 31) << 2);
}

__global__ __launch_bounds__(256, 2)
void moe_main(const float* __restrict__ X, float* __restrict__ out) {
    extern __shared__ unsigned sm[];
    const int tid = threadIdx.x, wid = tid >> 5, lane = tid & 31;
    const int gy = lane >> 2, gx = lane & 3;
    const int mw = wid >> 1, nw = wid & 1;
    const int r0 = mw * 16 + gy;
    const size_t rowbase = (size_t)blockIdx.x * 64;

    unsigned* Xp  = sm + U_XP;
    unsigned* W1s = sm + U_W1;
    unsigned* W2s = sm + U_W2;
    unsigned* W3s = sm + U_W3;
    unsigned* Wg  = sm + U_HA;   // alias: gates done before hA first written
    unsigned* hA  = sm + U_HA;
    unsigned* hB  = sm + U_HB;
    float* gts = reinterpret_cast<float*>(sm + U_GT);
    const uint32_t sb = smem_to_u32(sm);

    // ---- prefetch group 0: gate weights (needed first) ----
    {
        const uint4* sg = reinterpret_cast<const uint4*>(g_Wgp);
#pragma unroll
        for (int i = 0; i < 2; ++i)
            cp16(sb + (U_HA << 2) + (tid + i * 256) * 16, sg + tid + i * 256);
        CP_COMMIT();   // group 0
    }
    // ---- prefetch group 1: expert-0 weights ----
    {
        const uint4* s1 = reinterpret_cast<const uint4*>(g_W1p);
#pragma unroll
        for (int i = 0; i < 8; ++i)
            cp16(sb + (U_W1 << 2) + (tid + i * 256) * 16, s1 + tid + i * 256);
        const uint4* s2 = reinterpret_cast<const uint4*>(g_W2p);
#pragma unroll
        for (int i = 0; i < 2; ++i)
            cp16(sb + (U_W2 << 2) + (tid + i * 256) * 16, s2 + tid + i * 256);
        const uint4* s3 = reinterpret_cast<const uint4*>(g_W3p);
#pragma unroll
        for (int i = 0; i < 2; ++i)
            cp16(sb + (U_W3 << 2) + (tid + i * 256) * 16, s3 + tid + i * 256);
        CP_COMMIT();   // group 1
    }

    // ---- stage X: gmem (coalesced float4) -> packed fp16 A-frags ----
    {
        const float4* xg = reinterpret_cast<const float4*>(X + rowbase * 256);
#pragma unroll
        for (int it = 0; it < 16; ++it) {
            int g = tid + it * 256;              // float4 id, row-major
            float4 v = xg[g];
            int r = g >> 6, c4 = g & 63;
            int ks = c4 >> 2, kk = (c4 & 3) * 4; // kk in {0,4,8,12}
            int mt = r >> 4, rl = r & 15;
            int jr = (rl >= 8) ? 1 : 0, gyy = rl & 7;
            int gxp = (kk & 7) >> 1;             // 0 or 2
            int j0 = jr + ((kk & 8) ? 2 : 0);
            int blk = ks * 4 + mt;
            int fl0 = gyy * 4 + gxp;
            Xp[blk * 128 + (((fl0     + blk * 4) & 31) << 2) + j0] = packh2(v.x, v.y);
            Xp[blk * 128 + (((fl0 + 1 + blk * 4) & 31) << 2) + j0] = packh2(v.z, v.w);
        }
    }
    CP_WAIT1();        // group 0 (Wg) complete; expert-0 weights may still fly
    __syncthreads();

    // ---- gate logits via mma: warp (mw,nw) -> rows mw*16.., cols nw*8.. ----
    {
        float c[4] = {0.f, 0.f, 0.f, 0.f};
#pragma unroll
        for (int ks = 0; ks < 16; ++ks) {
            int blk = ks * 4 + mw;
            uint4 A = *reinterpret_cast<const uint4*>(Xp + xp_idx4(blk, lane));
            uint2 B = *reinterpret_cast<const uint2*>(Wg + (ks * 2 + nw) * 64 + lane * 2);
            mma16(c, A.x, A.y, A.z, A.w, B.x, B.y);
        }
        int col = nw * 8 + 2 * gx;
        gts[r0 * 17 + col]           = c[0] + g_bg[col];
        gts[r0 * 17 + col + 1]       = c[1] + g_bg[col + 1];
        gts[(r0 + 8) * 17 + col]     = c[2] + g_bg[col];
        gts[(r0 + 8) * 17 + col + 1] = c[3] + g_bg[col + 1];
    }
    __syncthreads();

    // ---- softmax per (row, task) over 8 logits ----
    if (tid < 128) {
        int r = tid >> 1, t = tid & 1;
        float* p = gts + r * 17 + t * 8;
        float m = p[0];
#pragma unroll
        for (int i = 1; i < 8; ++i) m = fmaxf(m, p[i]);
        float e8[8]; float s = 0.f;
#pragma unroll
        for (int i = 0; i < 8; ++i) { e8[i] = __expf(p[i] - m); s += e8[i]; }
        float inv = 1.f / s;
#pragma unroll
        for (int i = 0; i < 8; ++i) p[i] = e8[i] * inv;
    }
    CP_WAIT0();        // expert-0 weights complete
    __syncthreads();   // gts + staged weights visible CTA-wide

    float acc0[16], acc1[16];
#pragma unroll
    for (int i = 0; i < 16; ++i) { acc0[i] = 0.f; acc1[i] = 0.f; }

    // ---- expert loop (identical to the 182us R5 kernel) ----
    for (int e = 0; e < NE; ++e) {
        if (e) { CP_WAIT0(); __syncthreads(); }   // W1/W2/W3[e] ready+visible
        const unsigned* W3cur = W3s + (e & 1) * 2048;

        // L1: [64,256] x W1^T, K=256 -> 16 ksteps
        float c1[4][4] = {};
#pragma unroll
        for (int ks = 0; ks < 16; ++ks) {
            int blk = ks * 4 + mw;
            uint4 A = *reinterpret_cast<const uint4*>(Xp + xp_idx4(blk, lane));
#pragma unroll
            for (int nt = 0; nt < 4; ++nt) {
                uint2 B = *reinterpret_cast<const uint2*>(
                    W1s + (ks * 8 + nw * 4 + nt) * 64 + lane * 2);
                mma16(c1[nt], A.x, A.y, A.z, A.w, B.x, B.y);
            }
        }
        // epilogue 1: bias+relu -> hA in packed A-frag layout (STS.64/lane)
        {
            const float* b = g_b1 + e * 64;
#pragma unroll
            for (int nt = 0; nt < 4; ++nt) {
                int col = nw * 32 + nt * 8 + 2 * gx;
                float b0 = b[col], b1v = b[col + 1];
                unsigned lo = packh2(fmaxf(c1[nt][0] + b0, 0.f), fmaxf(c1[nt][1] + b1v, 0.f));
                unsigned hi = packh2(fmaxf(c1[nt][2] + b0, 0.f), fmaxf(c1[nt][3] + b1v, 0.f));
                int ksp = (nw * 4 + nt) >> 1, jb = (nt & 1) * 2;
                *reinterpret_cast<uint2*>(hA + (ksp * 4 + mw) * 128 + lane * 4 + jb) =
                    make_uint2(lo, hi);
            }
        }
        __syncthreads();                    // hA visible; W1s free
        if (e + 1 < NE) {
            const uint4* s1 = reinterpret_cast<const uint4*>(g_W1p) + (e + 1) * 2048;
#pragma unroll
            for (int i = 0; i < 8; ++i)
                cp16(sb + (U_W1 << 2) + (tid + i * 256) * 16, s1 + tid + i * 256);
        }
        CP_COMMIT();

        // L2: K=64 -> 4 ksteps
        float c2[4][4] = {};
#pragma unroll
        for (int ks = 0; ks < 4; ++ks) {
            uint4 A = *reinterpret_cast<const uint4*>(hA + (ks * 4 + mw) * 128 + lane * 4);
#pragma unroll
            for (int nt = 0; nt < 4; ++nt) {
                uint2 B = *reinterpret_cast<const uint2*>(
                    W2s + (ks * 8 + nw * 4 + nt) * 64 + lane * 2);
                mma16(c2[nt], A.x, A.y, A.z, A.w, B.x, B.y);
            }
        }
        {
            const float* b = g_b2 + e * 64;
#pragma unroll
            for (int nt = 0; nt < 4; ++nt) {
                int col = nw * 32 + nt * 8 + 2 * gx;
                float b0 = b[col], b1v = b[col + 1];
                unsigned lo = packh2(fmaxf(c2[nt][0] + b0, 0.f), fmaxf(c2[nt][1] + b1v, 0.f));
                unsigned hi = packh2(fmaxf(c2[nt][2] + b0, 0.f), fmaxf(c2[nt][3] + b1v, 0.f));
                int ksp = (nw * 4 + nt) >> 1, jb = (nt & 1) * 2;
                *reinterpret_cast<uint2*>(hB + (ksp * 4 + mw) * 128 + lane * 4 + jb) =
                    make_uint2(lo, hi);
            }
        }
        __syncthreads();                    // hB visible; W2s free
        if (e + 1 < NE) {
            const uint4* s2 = reinterpret_cast<const uint4*>(g_W2p) + (e + 1) * 512;
#pragma unroll
            for (int i = 0; i < 2; ++i)
                cp16(sb + (U_W2 << 2) + (tid + i * 256) * 16, s2 + tid + i * 256);
            const uint4* s3 = reinterpret_cast<const uint4*>(g_W3p) + (e + 1) * 512;
            uint32_t d3 = sb + ((U_W3 + ((e + 1) & 1) * 2048) << 2);
#pragma unroll
            for (int i = 0; i < 2; ++i)
                cp16(d3 + (tid + i * 256) * 16, s3 + tid + i * 256);
        }
        CP_COMMIT();

        // L3
        float c3[4][4] = {};
#pragma unroll
        for (int ks = 0; ks < 4; ++ks) {
            uint4 A = *reinterpret_cast<const uint4*>(hB + (ks * 4 + mw) * 128 + lane * 4);
#pragma unroll
            for (int nt = 0; nt < 4; ++nt) {
                uint2 B = *reinterpret_cast<const uint2*>(
                    W3cur + (ks * 8 + nw * 4 + nt) * 64 + lane * 2);
                mma16(c3[nt], A.x, A.y, A.z, A.w, B.x, B.y);
            }
        }
        // epilogue 3: bias + gated accumulate into registers
        {
            const float* b = g_b3 + e * 64;
            if (e < 8) {
                int t = e >> 2, gi = e & 3;
                float g0 = gts[r0 * 17 + t * 8 + gi];
                float g1 = gts[(r0 + 8) * 17 + t * 8 + gi];
                if (e < 4) {
#pragma unroll
                    for (int nt = 0; nt < 4; ++nt) {
                        int col = nw * 32 + nt * 8 + 2 * gx;
                        float b0 = b[col], b1v = b[col + 1];
                        acc0[nt * 4 + 0] += g0 * (c3[nt][0] + b0);
                        acc0[nt * 4 + 1] += g0 * (c3[nt][1] + b1v);
                        acc0[nt * 4 + 2] += g1 * (c3[nt][2] + b0);
                        acc0[nt * 4 + 3] += g1 * (c3[nt][3] + b1v);
                    }
                } else {
#pragma unroll
                    for (int nt = 0; nt < 4; ++nt) {
                        int col = nw * 32 + nt * 8 + 2 * gx;
                        float b0 = b[col], b1v = b[col + 1];
                        acc1[nt * 4 + 0] += g0 * (c3[nt][0] + b0);
                        acc1[nt * 4 + 1] += g0 * (c3[nt][1] + b1v);
                        acc1[nt * 4 + 2] += g1 * (c3[nt][2] + b0);
                        acc1[nt * 4 + 3] += g1 * (c3[nt][3] + b1v);
                    }
                }
            } else {
                float ga0 = gts[r0 * 17 + (e - 4)];
                float ga1 = gts[(r0 + 8) * 17 + (e - 4)];
                float gb0 = gts[r0 * 17 + (e + 4)];
                float gb1 = gts[(r0 + 8) * 17 + (e + 4)];
#pragma unroll
                for (int nt = 0; nt < 4; ++nt) {
                    int col = nw * 32 + nt * 8 + 2 * gx;
                    float b0 = b[col], b1v = b[col + 1];
                    float v0 = c3[nt][0] + b0, v1 = c3[nt][1] + b1v;
                    float v2 = c3[nt][2] + b0, v3 = c3[nt][3] + b1v;
                    acc0[nt * 4 + 0] += ga0 * v0; acc1[nt * 4 + 0] += gb0 * v0;
                    acc0[nt * 4 + 1] += ga0 * v1; acc1[nt * 4 + 1] += gb0 * v1;
                    acc0[nt * 4 + 2] += ga1 * v2; acc1[nt * 4 + 2] += gb1 * v2;
                    acc0[nt * 4 + 3] += ga1 * v3; acc1[nt * 4 + 3] += gb1 * v3;
                }
            }
        }
    }

    __syncthreads();
    // ---- output: stage fp32 to smem (stride 132), then coalesced float4 ----
    {
        float* ost = reinterpret_cast<float*>(sm + U_W1);
#pragma unroll
        for (int nt = 0; nt < 4; ++nt) {
            int col0 = nw * 32 + nt * 8 + 2 * gx;          // task 0
            *reinterpret_cast<float2*>(ost + r0 * 132 + col0) =
                make_float2(acc0[nt * 4 + 0], acc0[nt * 4 + 1]);
            *reinterpret_cast<float2*>(ost + (r0 + 8) * 132 + col0) =
                make_float2(acc0[nt * 4 + 2], acc0[nt * 4 + 3]);
            int col1 = 64 + col0;                          // task 1
            *reinterpret_cast<float2*>(ost + r0 * 132 + col1) =
                make_float2(acc1[nt * 4 + 0], acc1[nt * 4 + 1]);
            *reinterpret_cast<float2*>(ost + (r0 + 8) * 132 + col1) =
                make_float2(acc1[nt * 4 + 2], acc1[nt * 4 + 3]);
        }
    }
    __syncthreads();
    {
        float4* og = reinterpret_cast<float4*>(out + rowbase * 128);
        const float* ost = reinterpret_cast<const float*>(sm + U_W1);
#pragma unroll
        for (int it = 0; it < 8; ++it) {
            int g = tid + it * 256;
            int rr = g >> 5, q = g & 31;
            og[g] = *reinterpret_cast<const float4*>(ost + rr * 132 + q * 4);
        }
    }
}

// ------------------------------- launcher ----------------------------------
extern "C" void kernel_launch(void* const* d_in, const int* in_sizes, int n_in,
                              void* d_out, int out_size) {
    const float* X   = (const float*)d_in[0];
    const float* Wt1 = (const float*)d_in[1];
    const float* bt1 = (const float*)d_in[2];
    const float* Wt2 = (const float*)d_in[3];
    const float* bt2 = (const float*)d_in[4];
    const float* Wt3 = (const float*)d_in[5];
    const float* bt3 = (const float*)d_in[6];
    const float* Ws1 = (const float*)d_in[7];
    const float* bs1 = (const float*)d_in[8];
    const float* Ws2 = (const float*)d_in[9];
    const float* bs2 = (const float*)d_in[10];
    const float* Ws3 = (const float*)d_in[11];
    const float* bs3 = (const float*)d_in[12];
    const float* Wg  = (const float*)d_in[13];
    const float* bg  = (const float*)d_in[14];
    float* out = (float*)d_out;

    pack_all<<<(PK_END + 255) / 256, 256>>>(Wt1, Wt2, Wt3, Ws1, Ws2, Ws3, Wg,
                                            bt1, bt2, bt3, bs1, bs2, bs3, bg);

    cudaFuncSetAttribute(moe_main, cudaFuncAttributeMaxDynamicSharedMemorySize,
                         U_TOT * (int)sizeof(unsigned));
    moe_main<<<65536 / 64, 256, U_TOT * sizeof(unsigned)>>>(X, out);
}

// round 9
// speedup vs baseline: 1.6659x; 1.1043x over previous
#include <cuda_runtime.h>
#include <cuda_fp16.h>
#include <cstdint>

// ---------------------------------------------------------------------------
// ExtractNet (MMoE/PLE): 12 expert MLPs (256->64->64->64) + per-task softmax
// gates. fp16 mma.sync.m16n8k16, fp32 accum.
// Full-chain-per-warp design: each warp owns 16 rows x all 64 cols and runs
// L1->relu->L2->relu->L3 entirely in registers (in-lane C->A fragment
// conversion). X A-frags register-cached across all experts. 128 thr/CTA,
// 64 rows/CTA, 2 CTA/SM. Only L1 traffic left: weight B-fragments.
// ---------------------------------------------------------------------------

#define NE 12

// Packed weights: u32 = half2 in exact B-fragment order
__device__ unsigned g_W1p[NE * 8192];   // per expert: 16ks x 8nt x 64
__device__ unsigned g_W2p[NE * 2048];   // 4ks x 8nt x 64
__device__ unsigned g_W3p[NE * 2048];
__device__ unsigned g_Wgp[2048];        // gates: 16ks x 2slot x 64
__device__ float g_b1[NE * 64];
__device__ float g_b2[NE * 64];
__device__ float g_b3[NE * 64];
__device__ float g_bg[16];

__device__ __forceinline__ unsigned packh2(float a, float b) {
    __half2 h = __floats2half2_rn(a, b);
    return *reinterpret_cast<unsigned*>(&h);
}

__device__ __forceinline__ uint32_t smem_to_u32(const void* p) {
    uint32_t a;
    asm("{ .reg .u64 t; cvta.to.shared.u64 t, %1; cvt.u32.u64 %0, t; }"
        : "=r"(a) : "l"(p));
    return a;
}

// m16n8k16 fp16 mma, fp32 accum.  lane = gy*4+gx
// A: a0={A[gy][2gx],A[gy][2gx+1]} a1={A[gy+8][..]} a2={A[gy][2gx+8],..} a3={A[gy+8][2gx+8],..}
// B: b0={B[2gx][n],B[2gx+1][n]} b1={B[2gx+8][n],B[2gx+9][n]}, n=gy
// C: c0=(gy,2gx) c1=(gy,2gx+1) c2=(gy+8,2gx) c3=(gy+8,2gx+1)
__device__ __forceinline__ void mma16(float c[4], unsigned a0, unsigned a1,
                                      unsigned a2, unsigned a3,
                                      unsigned b0, unsigned b1) {
    asm volatile(
        "mma.sync.aligned.m16n8k16.row.col.f32.f16.f16.f32 "
        "{%0,%1,%2,%3}, {%4,%5,%6,%7}, {%8,%9}, {%0,%1,%2,%3};\n"
        : "+f"(c[0]), "+f"(c[1]), "+f"(c[2]), "+f"(c[3])
        : "r"(a0), "r"(a1), "r"(a2), "r"(a3), "r"(b0), "r"(b1));
}

__device__ __forceinline__ void cp16(uint32_t dst, const void* src) {
    asm volatile("cp.async.cg.shared.global [%0], [%1], 16;" :: "r"(dst), "l"(src));
}
#define CP_COMMIT() asm volatile("cp.async.commit_group;" ::: "memory")
#define CP_WAIT0()  asm volatile("cp.async.wait_group 0;" ::: "memory")
#define CP_WAIT1()  asm volatile("cp.async.wait_group 1;" ::: "memory")

// ------------------------- fused weight packing ----------------------------
#define PK_W1 (NE * 8192)
#define PK_W2 (PK_W1 + NE * 2048)
#define PK_W3 (PK_W2 + NE * 2048)
#define PK_WG (PK_W3 + 2048)
#define PK_END (PK_WG + 2320)

__global__ void pack_all(const float* __restrict__ Wt1, const float* __restrict__ Wt2,
                         const float* __restrict__ Wt3, const float* __restrict__ Ws1,
                         const float* __restrict__ Ws2, const float* __restrict__ Ws3,
                         const float* __restrict__ Wg,
                         const float* __restrict__ bt1, const float* __restrict__ bt2,
                         const float* __restrict__ bt3, const float* __restrict__ bs1,
                         const float* __restrict__ bs2, const float* __restrict__ bs3,
                         const float* __restrict__ bg) {
    int idx = blockIdx.x * blockDim.x + threadIdx.x;
    if (idx < PK_W1) {
        int e = idx >> 13, p = idx & 8191;
        int ks = p >> 9, rem = p & 511, nt = rem >> 6, q = rem & 63;
        int lane = q >> 1, j = q & 1;
        int gy = lane >> 2, gx = lane & 3;
        int k0 = ks * 16 + j * 8 + 2 * gx, n = nt * 8 + gy;
        const float* src = (e < 8) ? Wt1 + e * 16384 : Ws1 + (e - 8) * 16384;
        g_W1p[idx] = packh2(src[k0 * 64 + n], src[(k0 + 1) * 64 + n]);
    } else if (idx < PK_W3) {
        int which = (idx >= PK_W2);
        int i2 = idx - (which ? PK_W2 : PK_W1);
        int e = i2 >> 11, p = i2 & 2047;
        int ks = p >> 9, rem = p & 511, nt = rem >> 6, q = rem & 63;
        int lane = q >> 1, j = q & 1;
        int gy = lane >> 2, gx = lane & 3;
        int k0 = ks * 16 + j * 8 + 2 * gx, n = nt * 8 + gy;
        const float* wt = which ? Wt3 : Wt2;
        const float* ws = which ? Ws3 : Ws2;
        const float* src = (e < 8) ? wt + e * 4096 : ws + (e - 8) * 4096;
        unsigned v = packh2(src[k0 * 64 + n], src[(k0 + 1) * 64 + n]);
        if (which) g_W3p[i2] = v; else g_W2p[i2] = v;
    } else if (idx < PK_WG) {
        int i2 = idx - PK_W3;
        int ks = i2 >> 7, rem = i2 & 127, t = rem >> 6, q = rem & 63;
        int lane = q >> 1, j = q & 1;
        int gy = lane >> 2, gx = lane & 3;
        int k0 = ks * 16 + j * 8 + 2 * gx;
        g_Wgp[i2] = packh2(Wg[t * 2048 + k0 * 8 + gy], Wg[t * 2048 + (k0 + 1) * 8 + gy]);
    } else if (idx < PK_END) {
        int i = idx - PK_WG;
        if (i < 768) g_b1[i] = (i < 512) ? bt1[i] : bs1[i - 512];
        else if (i < 1536) { int j = i - 768;  g_b2[j] = (j < 512) ? bt2[j] : bs2[j - 512]; }
        else if (i < 2304) { int j = i - 1536; g_b3[j] = (j < 512) ? bt3[j] : bs3[j - 512]; }
        else g_bg[i - 2304] = bg[i - 2304];
    }
}

// ------------------------------ main kernel --------------------------------
// smem u32 offsets (total 27984 u32 = 111,936 B -> 2 CTAs/SM)
#define U_R0 0        // 8192: X A-frags initially; W1 odd-buffer; out staging
#define U_R1 8192     // 8192: W1 even-buffer
#define U_W2 16384    // 2 x 2048 (buf1 holds Wg during gate phase)
#define U_W3 20480    // 2 x 2048
#define U_GT 24576    // 1088 floats (gate probs, 64 rows x stride 17)
#define U_B  25664    // 2320 floats: b1 768 | b2 768 | b3 768 | bg 16
#define U_TOT 27984

__device__ __forceinline__ float relu(float x) { return fmaxf(x, 0.f); }

__global__ __launch_bounds__(128, 2)
void moe_main(const float* __restrict__ X, float* __restrict__ out) {
    extern __shared__ unsigned sm[];
    const int tid = threadIdx.x, w = tid >> 5, lane = tid & 31;
    const int gy = lane >> 2, gx = lane & 3;
    const size_t rowbase = (size_t)blockIdx.x * 64;

    unsigned* Xp = sm + U_R0;
    float* gts  = reinterpret_cast<float*>(sm + U_GT);
    float* bias = reinterpret_cast<float*>(sm + U_B);
    const uint32_t sb = smem_to_u32(sm);

    // ---- prefetch group 0: gate weights -> W2 buf1 ----
    {
        const uint4* sg = reinterpret_cast<const uint4*>(g_Wgp);
#pragma unroll
        for (int i = 0; i < 4; ++i)
            cp16(sb + ((U_W2 + 2048) << 2) + (tid + i * 128) * 16, sg + tid + i * 128);
        CP_COMMIT();
    }
    // ---- prefetch group 1: expert-0 weights (W1->R1, W2->buf0, W3->buf0) ----
    {
        const uint4* s1 = reinterpret_cast<const uint4*>(g_W1p);
#pragma unroll
        for (int i = 0; i < 16; ++i)
            cp16(sb + (U_R1 << 2) + (tid + i * 128) * 16, s1 + tid + i * 128);
        const uint4* s2 = reinterpret_cast<const uint4*>(g_W2p);
#pragma unroll
        for (int i = 0; i < 4; ++i)
            cp16(sb + (U_W2 << 2) + (tid + i * 128) * 16, s2 + tid + i * 128);
        const uint4* s3 = reinterpret_cast<const uint4*>(g_W3p);
#pragma unroll
        for (int i = 0; i < 4; ++i)
            cp16(sb + (U_W3 << 2) + (tid + i * 128) * 16, s3 + tid + i * 128);
        CP_COMMIT();
    }

    // ---- stage biases (plain loads) ----
    for (int i = tid; i < 768; i += 128) {
        bias[i]        = g_b1[i];
        bias[768 + i]  = g_b2[i];
        bias[1536 + i] = g_b3[i];
    }
    if (tid < 16) bias[2304 + tid] = g_bg[tid];

    // ---- stage X -> A-fragment layout in Xp (frag-rotated, one-time) ----
    {
        const float4* xg = reinterpret_cast<const float4*>(X + rowbase * 256);
#pragma unroll
        for (int it = 0; it < 32; ++it) {
            int g = tid + it * 128;               // float4 id (64 rows x 64)
            float4 v = xg[g];
            int r = g >> 6, c4 = g & 63;
            int wr = r >> 4, gyy = r & 7, jr = (r & 15) >> 3;
            int ks = c4 >> 2, cc0 = (c4 & 3) * 4;
            int lane0 = gyy * 4 + ((cc0 & 7) >> 1);
            int j = jr + ((cc0 & 8) ? 2 : 0);
            int frag = wr * 16 + ks;
            unsigned* base = Xp + frag * 128;
            base[(((lane0)     + frag) & 31) * 4 + j] = packh2(v.x, v.y);
            base[(((lane0 + 1) + frag) & 31) * 4 + j] = packh2(v.z, v.w);
        }
    }
    CP_WAIT1();        // group 0 (Wg) landed
    __syncthreads();   // Xp + biases visible

    // ---- register-cache ALL X A-frags for this warp's 16 rows ----
    uint4 XA[16];
#pragma unroll
    for (int ks = 0; ks < 16; ++ks) {
        int frag = w * 16 + ks;
        XA[ks] = *reinterpret_cast<const uint4*>(
            Xp + frag * 128 + (((lane + frag) & 31) << 2));
    }

    // ---- gate logits (warp-local): m16 x n16, K=256 ----
    {
        const unsigned* Wgs = sm + U_W2 + 2048;
        float cg[2][4] = {};
#pragma unroll
        for (int ks = 0; ks < 16; ++ks) {
            uint4 A = XA[ks];
#pragma unroll
            for (int s = 0; s < 2; ++s) {
                uint2 B = *reinterpret_cast<const uint2*>(Wgs + (ks * 2 + s) * 64 + lane * 2);
                mma16(cg[s], A.x, A.y, A.z, A.w, B.x, B.y);
            }
        }
        int r0 = w * 16 + gy;
#pragma unroll
        for (int s = 0; s < 2; ++s) {
            int col = s * 8 + 2 * gx;
            gts[r0 * 17 + col]           = cg[s][0] + bias[2304 + col];
            gts[r0 * 17 + col + 1]       = cg[s][1] + bias[2304 + col + 1];
            gts[(r0 + 8) * 17 + col]     = cg[s][2] + bias[2304 + col];
            gts[(r0 + 8) * 17 + col + 1] = cg[s][3] + bias[2304 + col + 1];
        }
        __syncwarp();
        // softmax: lane l -> row w*16 + (l>>1), task l&1
        {
            int r = w * 16 + (lane >> 1), t = lane & 1;
            float* p = gts + r * 17 + t * 8;
            float m = p[0];
#pragma unroll
            for (int i = 1; i < 8; ++i) m = fmaxf(m, p[i]);
            float e8[8]; float s = 0.f;
#pragma unroll
            for (int i = 0; i < 8; ++i) { e8[i] = __expf(p[i] - m); s += e8[i]; }
            float inv = 1.f / s;
#pragma unroll
            for (int i = 0; i < 8; ++i) p[i] = e8[i] * inv;
        }
        __syncwarp();
    }

    float acc[64];     // [task][nt][4] = t*32 + nt*4 + j
#pragma unroll
    for (int i = 0; i < 64; ++i) acc[i] = 0.f;

    const int rr0 = (w * 16 + gy) * 17, rr1 = (w * 16 + gy + 8) * 17;

    // ---- expert loop: full chain per warp, h in registers ----
    for (int e = 0; e < NE; ++e) {
        CP_WAIT0();
        __syncthreads();   // expert e weights visible; e-1 buffers retired
        const unsigned* W1s = sm + ((e & 1) ? U_R0 : U_R1);
        const unsigned* W2s = sm + U_W2 + (e & 1) * 2048;
        const unsigned* W3s = sm + U_W3 + (e & 1) * 2048;

        if (e + 1 < NE) {  // prefetch e+1 into opposite buffers
            int nb = (e + 1) & 1;
            const uint4* s1 = reinterpret_cast<const uint4*>(g_W1p) + (e + 1) * 2048;
            uint32_t d1 = sb + ((nb ? U_R0 : U_R1) << 2);
#pragma unroll
            for (int i = 0; i < 16; ++i)
                cp16(d1 + (tid + i * 128) * 16, s1 + tid + i * 128);
            const uint4* s2 = reinterpret_cast<const uint4*>(g_W2p) + (e + 1) * 512;
            uint32_t d2 = sb + ((U_W2 + nb * 2048) << 2);
#pragma unroll
            for (int i = 0; i < 4; ++i)
                cp16(d2 + (tid + i * 128) * 16, s2 + tid + i * 128);
            const uint4* s3 = reinterpret_cast<const uint4*>(g_W3p) + (e + 1) * 512;
            uint32_t d3 = sb + ((U_W3 + nb * 2048) << 2);
#pragma unroll
            for (int i = 0; i < 4; ++i)
                cp16(d3 + (tid + i * 128) * 16, s3 + tid + i * 128);
            CP_COMMIT();
        }

        // L1: m16 x n64, K=256 (16 ksteps), A from registers
        float c1[8][4] = {};
#pragma unroll
        for (int ks = 0; ks < 16; ++ks) {
            uint4 A = XA[ks];
#pragma unroll
            for (int nt = 0; nt < 8; ++nt) {
                uint2 B = *reinterpret_cast<const uint2*>(
                    W1s + (ks * 8 + nt) * 64 + lane * 2);
                mma16(c1[nt], A.x, A.y, A.z, A.w, B.x, B.y);
            }
        }
        // bias+relu -> L2 A-frags, fully in-lane
        unsigned h1[4][4];
        {
            const float* b = bias + e * 64;
#pragma unroll
            for (int k2 = 0; k2 < 4; ++k2) {
                int na = 2 * k2, nb2 = 2 * k2 + 1;
                float ba0 = b[na * 8 + 2 * gx],  ba1 = b[na * 8 + 2 * gx + 1];
                float bb0 = b[nb2 * 8 + 2 * gx], bb1 = b[nb2 * 8 + 2 * gx + 1];
                h1[k2][0] = packh2(relu(c1[na][0] + ba0),  relu(c1[na][1] + ba1));
                h1[k2][1] = packh2(relu(c1[na][2] + ba0),  relu(c1[na][3] + ba1));
                h1[k2][2] = packh2(relu(c1[nb2][0] + bb0), relu(c1[nb2][1] + bb1));
                h1[k2][3] = packh2(relu(c1[nb2][2] + bb0), relu(c1[nb2][3] + bb1));
            }
        }

        // L2: K=64 (4 ksteps), A = h1 registers
        float c2[8][4] = {};
#pragma unroll
        for (int k2 = 0; k2 < 4; ++k2) {
#pragma unroll
            for (int nt = 0; nt < 8; ++nt) {
                uint2 B = *reinterpret_cast<const uint2*>(
                    W2s + (k2 * 8 + nt) * 64 + lane * 2);
                mma16(c2[nt], h1[k2][0], h1[k2][1], h1[k2][2], h1[k2][3], B.x, B.y);
            }
        }
        unsigned h2[4][4];
        {
            const float* b = bias + 768 + e * 64;
#pragma unroll
            for (int k2 = 0; k2 < 4; ++k2) {
                int na = 2 * k2, nb2 = 2 * k2 + 1;
                float ba0 = b[na * 8 + 2 * gx],  ba1 = b[na * 8 + 2 * gx + 1];
                float bb0 = b[nb2 * 8 + 2 * gx], bb1 = b[nb2 * 8 + 2 * gx + 1];
                h2[k2][0] = packh2(relu(c2[na][0] + ba0),  relu(c2[na][1] + ba1));
                h2[k2][1] = packh2(relu(c2[na][2] + ba0),  relu(c2[na][3] + ba1));
                h2[k2][2] = packh2(relu(c2[nb2][0] + bb0), relu(c2[nb2][1] + bb1));
                h2[k2][3] = packh2(relu(c2[nb2][2] + bb0), relu(c2[nb2][3] + bb1));
            }
        }

        // L3
        float c3[8][4] = {};
#pragma unroll
        for (int k2 = 0; k2 < 4; ++k2) {
#pragma unroll
            for (int nt = 0; nt < 8; ++nt) {
                uint2 B = *reinterpret_cast<const uint2*>(
                    W3s + (k2 * 8 + nt) * 64 + lane * 2);
                mma16(c3[nt], h2[k2][0], h2[k2][1], h2[k2][2], h2[k2][3], B.x, B.y);
            }
        }

        // bias + gated accumulate
        {
            const float* b = bias + 1536 + e * 64;
            if (e < 8) {
                int t = e >> 2, gi = e & 3;
                float g0 = gts[rr0 + t * 8 + gi];
                float g1 = gts[rr1 + t * 8 + gi];
                float* ac = acc + t * 32;
#pragma unroll
                for (int nt = 0; nt < 8; ++nt) {
                    float b0 = b[nt * 8 + 2 * gx], b1v = b[nt * 8 + 2 * gx + 1];
                    ac[nt * 4 + 0] += g0 * (c3[nt][0] + b0);
                    ac[nt * 4 + 1] += g0 * (c3[nt][1] + b1v);
                    ac[nt * 4 + 2] += g1 * (c3[nt][2] + b0);
                    ac[nt * 4 + 3] += g1 * (c3[nt][3] + b1v);
                }
            } else {
                float ga0 = gts[rr0 + (e - 4)], ga1 = gts[rr1 + (e - 4)];
                float gb0 = gts[rr0 + (e + 4)], gb1 = gts[rr1 + (e + 4)];
#pragma unroll
                for (int nt = 0; nt < 8; ++nt) {
                    float b0 = b[nt * 8 + 2 * gx], b1v = b[nt * 8 + 2 * gx + 1];
                    float v0 = c3[nt][0] + b0, v1 = c3[nt][1] + b1v;
                    float v2 = c3[nt][2] + b0, v3 = c3[nt][3] + b1v;
                    acc[nt * 4 + 0]      += ga0 * v0; acc[32 + nt * 4 + 0] += gb0 * v0;
                    acc[nt * 4 + 1]      += ga0 * v1; acc[32 + nt * 4 + 1] += gb0 * v1;
                    acc[nt * 4 + 2]      += ga1 * v2; acc[32 + nt * 4 + 2] += gb1 * v2;
                    acc[nt * 4 + 3]      += ga1 * v3; acc[32 + nt * 4 + 3] += gb1 * v3;
                }
            }
        }
    }

    __syncthreads();
    // ---- output: stage fp32 (stride 132) then coalesced float4 ----
    {
        float* ost = reinterpret_cast<float*>(sm);   // R0+R1 free
        int r0 = w * 16 + gy;
#pragma unroll
        for (int t = 0; t < 2; ++t)
#pragma unroll
            for (int nt = 0; nt < 8; ++nt) {
                int col = t * 64 + nt * 8 + 2 * gx;
                *reinterpret_cast<float2*>(ost + r0 * 132 + col) =
                    make_float2(acc[t * 32 + nt * 4 + 0], acc[t * 32 + nt * 4 + 1]);
                *reinterpret_cast<float2*>(ost + (r0 + 8) * 132 + col) =
                    make_float2(acc[t * 32 + nt * 4 + 2], acc[t * 32 + nt * 4 + 3]);
            }
    }
    __syncthreads();
    {
        float4* og = reinterpret_cast<float4*>(out + rowbase * 128);
        const float* ost = reinterpret_cast<const float*>(sm);
#pragma unroll
        for (int it = 0; it < 16; ++it) {
            int g = tid + it * 128;
            int rr = g >> 5, q = g & 31;
            og[g] = *reinterpret_cast<const float4*>(ost + rr * 132 + q * 4);
        }
    }
}

// ------------------------------- launcher ----------------------------------
extern "C" void kernel_launch(void* const* d_in, const int* in_sizes, int n_in,
                              void* d_out, int out_size) {
    const float* X   = (const float*)d_in[0];
    const float* Wt1 = (const float*)d_in[1];
    const float* bt1 = (const float*)d_in[2];
    const float* Wt2 = (const float*)d_in[3];
    const float* bt2 = (const float*)d_in[4];
    const float* Wt3 = (const float*)d_in[5];
    const float* bt3 = (const float*)d_in[6];
    const float* Ws1 = (const float*)d_in[7];
    const float* bs1 = (const float*)d_in[8];
    const float* Ws2 = (const float*)d_in[9];
    const float* bs2 = (const float*)d_in[10];
    const float* Ws3 = (const float*)d_in[11];
    const float* bs3 = (const float*)d_in[12];
    const float* Wg  = (const float*)d_in[13];
    const float* bg  = (const float*)d_in[14];
    float* out = (float*)d_out;

    pack_all<<<(PK_END + 255) / 256, 256>>>(Wt1, Wt2, Wt3, Ws1, Ws2, Ws3, Wg,
                                            bt1, bt2, bt3, bs1, bs2, bs3, bg);

    cudaFuncSetAttribute(moe_main, cudaFuncAttributeMaxDynamicSharedMemorySize,
                         U_TOT * (int)sizeof(unsigned));
    moe_main<<<65536 / 64, 128, U_TOT * sizeof(unsigned)>>>(X, out);
}